// round 14
// baseline (speedup 1.0000x reference)
#include <cuda_runtime.h>
#include <cuda_bf16.h>
#include <cooperative_groups.h>
namespace cg = cooperative_groups;

constexpr int NN  = 20000;   // nodes
constexpr int TT  = 12;      // encoder steps
constexpr int HOR = 6;       // decoder horizon
constexpr int FF  = 16;      // input features (== C, decoder feedback)
constexpr int EE  = 320000;  // edges
constexpr int HH  = 128;     // hidden
constexpr int CC  = 16;      // out channels

// ---------------- scratch (static device globals; no allocation) -----------
__device__ __align__(16) float g_W[384 * HH];         // fused [A;B;C] fp32
__device__ __align__(16) float g_dvec[HH];            // fused bias vector
__device__ __align__(16) unsigned g_Whi_pk[192 * HH]; // bf16x2-packed hi(W)
__device__ __align__(16) unsigned g_Wlo_pk[192 * HH]; // bf16x2-packed lo(W)

// big encoder weight (packed directly by k_Rchain) and biases
__device__ __align__(16) float g_bbig[2][HH];         // bias(10), bias(11)
__device__ __align__(16) unsigned g_Wt_hi[2][768 * HH];
__device__ __align__(16) unsigned g_Wt_lo[2][768 * HH];

// pre-packed bf16 hi/lo activations
__device__ __align__(16) unsigned g_hg12h[TT][NN * 64];
__device__ __align__(16) unsigned g_hg12l[TT][NN * 64];
__device__ __align__(16) unsigned g_hbh[3][NN * 64];
__device__ __align__(16) unsigned g_hbl[3][NN * 64];
__device__ __align__(16) unsigned g_aggh[NN * 64];
__device__ __align__(16) unsigned g_aggl[NN * 64];
__device__ int   g_is64;

// per-edge-set CSR (built once per launch)
__device__ int   g_deg[TT][NN];
__device__ int   g_indptr[TT][NN + 1];
__device__ int   g_cur[TT][NN];
__device__ float g_dinv[TT][NN];
__device__ __align__(8) int2 g_epk[TT][EE];           // packed (src, w_bits)
__device__ int   g_psum[TT][10];

// ---------------- helpers ----------------------------------------------------
__device__ __forceinline__ unsigned pk_bf(__nv_bfloat16 a, __nv_bfloat16 b) {
    __nv_bfloat162 x; x.x = a; x.y = b;
    return *reinterpret_cast<unsigned*>(&x);
}
__device__ __forceinline__ void split_pk(float a, float b,
                                         unsigned& hi, unsigned& lo) {
    __nv_bfloat16 ha = __float2bfloat16(a);
    __nv_bfloat16 hb = __float2bfloat16(b);
    __nv_bfloat16 la = __float2bfloat16(a - __bfloat162float(ha));
    __nv_bfloat16 lb = __float2bfloat16(b - __bfloat162float(hb));
    hi = pk_bf(ha, hb);
    lo = pk_bf(la, lb);
}

__device__ __forceinline__ int load_idx(const void* p, long long e) {
    int v;
    if (g_is64) v = (int)((const long long*)p)[e];
    else        v = ((const int*)p)[e];
    v = v < 0 ? 0 : (v >= NN ? NN - 1 : v);
    return v;
}

// ---------------- launch 1: detect dtype + zero degree arrays ---------------
__global__ void k_init(const unsigned* __restrict__ w) {
    long long idx = (long long)blockIdx.x * blockDim.x + threadIdx.x;
    if (idx < (long long)TT * NN) (&g_deg[0][0])[idx] = 0;
    if (idx == 0) {
        int nz = 0;
        #pragma unroll 8
        for (int i = 0; i < 128; ++i) nz += (w[2 * i + 1] != 0u);
        g_is64 = (nz == 0) ? 1 : 0;
    }
}

// ---------------- launch 2: fold conv/proj -> W (fp32 + bf16 split), dvec ---
__global__ void k_prepWsd(const float* __restrict__ conv_w,
                          const float* __restrict__ proj_w,
                          const float* __restrict__ conv_b,
                          const float* __restrict__ proj_b) {
    int h = threadIdx.x;
    if (blockIdx.x == 192) {             // dvec
        float acc = proj_b[h];
        #pragma unroll 4
        for (int j = 0; j < 384; ++j) acc += conv_b[j] * proj_w[h * 384 + j];
        g_dvec[h] = acc;
        return;
    }
    __shared__ float wa[6][128];
    int kp = blockIdx.x;                 // 0..191
    int c0 = 2 * kp, c1 = c0 + 1;
    float a0 = 0.f, a1 = 0.f;
    if (c0 < 128) {
        wa[0][h] = conv_w[((128 + h) * 128 + c0) * 3 + 0];
        wa[1][h] = conv_w[((128 + h) * 128 + c1) * 3 + 0];
        __syncthreads();
        #pragma unroll 4
        for (int o = 0; o < 128; ++o) {
            float p = proj_w[h * 384 + 128 + o];
            a0 += wa[0][o] * p; a1 += wa[1][o] * p;
        }
    } else if (c0 < 256) {
        int cc0 = c0 - 128, cc1 = c1 - 128;
        wa[0][h] = conv_w[(h * 128 + cc0) * 3 + 0];
        wa[1][h] = conv_w[(h * 128 + cc1) * 3 + 0];
        __syncthreads();
        #pragma unroll 4
        for (int o = 0; o < 128; ++o) {
            float p = proj_w[h * 384 + o];
            a0 += wa[0][o] * p; a1 += wa[1][o] * p;
        }
    } else {
        int cc0 = c0 - 256, cc1 = c1 - 256;
        wa[0][h] = conv_w[(h * 128 + cc0) * 3 + 1];
        wa[1][h] = conv_w[((128 + h) * 128 + cc0) * 3 + 1];
        wa[2][h] = conv_w[((256 + h) * 128 + cc0) * 3 + 1];
        wa[3][h] = conv_w[(h * 128 + cc1) * 3 + 1];
        wa[4][h] = conv_w[((128 + h) * 128 + cc1) * 3 + 1];
        wa[5][h] = conv_w[((256 + h) * 128 + cc1) * 3 + 1];
        __syncthreads();
        #pragma unroll 2
        for (int o = 0; o < 128; ++o) {
            float p0 = proj_w[h * 384 + o];
            float p1 = proj_w[h * 384 + 128 + o];
            float p2 = proj_w[h * 384 + 256 + o];
            a0 += wa[0][o] * p0 + wa[1][o] * p1 + wa[2][o] * p2;
            a1 += wa[3][o] * p0 + wa[4][o] * p1 + wa[5][o] * p2;
        }
    }
    g_W[c0 * 128 + h] = a0;
    g_W[c1 * 128 + h] = a1;
    unsigned hi, lo;
    split_pk(a0, a1, hi, lo);
    g_Whi_pk[kp * 128 + h] = hi;
    g_Wlo_pk[kp * 128 + h] = lo;
}

// ---------------- CSR construction ----------------------------------------
__global__ void k_count12(const void* __restrict__ ei) {
    long long idx = (long long)blockIdx.x * blockDim.x + threadIdx.x;
    if (idx >= (long long)TT * EE) return;
    int set = (int)(idx / EE);
    int e   = (int)(idx % EE);
    int d = load_idx(ei, (long long)set * 2 * EE + EE + e);
    atomicAdd(&g_deg[set][d], 1);
}

__global__ void k_scanA() {
    __shared__ int wsum[8];
    int set = blockIdx.y, chunk = blockIdx.x;
    int t = threadIdx.x, lane = t & 31, wid = t >> 5;
    int base = chunk * 2000;
    int acc = 0;
    for (int j = t; j < 2000; j += 256) acc += g_deg[set][base + j];
    #pragma unroll
    for (int d = 16; d > 0; d >>= 1) acc += __shfl_down_sync(~0u, acc, d);
    if (lane == 0) wsum[wid] = acc;
    __syncthreads();
    if (t == 0) {
        int s = 0;
        #pragma unroll
        for (int w = 0; w < 8; ++w) s += wsum[w];
        g_psum[set][chunk] = s;
    }
}

__global__ void k_scanB() {
    __shared__ int sm[2048];
    __shared__ int woff[8];
    __shared__ int s_off;
    int set = blockIdx.y, chunk = blockIdx.x;
    int t = threadIdx.x, lane = t & 31, wid = t >> 5;
    int base = chunk * 2000;
    if (t == 0) {
        int o = 0;
        for (int c = 0; c < chunk; ++c) o += g_psum[set][c];
        s_off = o;
    }
    for (int j = t; j < 2048; j += 256)
        sm[j] = (j < 2000) ? g_deg[set][base + j] : 0;
    __syncthreads();
    int v[8];
    int run = 0;
    #pragma unroll
    for (int i = 0; i < 8; ++i) { v[i] = sm[t * 8 + i]; run += v[i]; }
    int x = run;
    #pragma unroll
    for (int d = 1; d < 32; d <<= 1) {
        int y = __shfl_up_sync(~0u, x, d);
        if (lane >= d) x += y;
    }
    if (lane == 31) woff[wid] = x;
    __syncthreads();
    if (t == 0) {
        int o = 0;
        #pragma unroll
        for (int w = 0; w < 8; ++w) { int tmp = woff[w]; woff[w] = o; o += tmp; }
    }
    __syncthreads();
    int runp = s_off + woff[wid] + (x - run);
    #pragma unroll
    for (int i = 0; i < 8; ++i) {
        int j = t * 8 + i;
        if (j < 2000) {
            int n = base + j;
            g_indptr[set][n] = runp;
            g_cur[set][n]    = runp;
            g_dinv[set][n]   = rsqrtf(1.0f + (float)v[i]);
            runp += v[i];
        }
    }
    if (chunk == 9 && t == 249) g_indptr[set][NN] = runp;
}

__global__ void k_fill12(const void* __restrict__ ei) {
    long long idx = (long long)blockIdx.x * blockDim.x + threadIdx.x;
    if (idx >= (long long)TT * EE) return;
    int set = (int)(idx / EE);
    int e   = (int)(idx % EE);
    long long b = (long long)set * 2 * EE;
    int s = load_idx(ei, b + e);
    int d = load_idx(ei, b + EE + e);
    int pos = atomicAdd(&g_cur[set][d], 1);
    float w = g_dinv[set][s] * g_dinv[set][d];
    g_epk[set][pos] = make_int2(s, __float_as_int(w));
}

// ---------------- fused GCN (16 nodes / 128 threads) — encoder batch ---------
__device__ __forceinline__ void gcn_body(const float* __restrict__ x, int set,
                                         unsigned* __restrict__ outh,
                                         unsigned* __restrict__ outl,
                                         const float* __restrict__ gcn_w,
                                         const float* __restrict__ gcn_b,
                                         int row0) {
    __shared__ float Xs[16 * 16];
    __shared__ float Ws[16 * 128];
    int tid = threadIdx.x;
    #pragma unroll
    for (int i = 0; i < 16; ++i) Ws[i * 128 + tid] = gcn_w[i * 128 + tid];

    int lane   = tid & 31;
    int nlocal = (tid >> 5) * 4 + (lane >> 3);
    int f2     = lane & 7;
    int node   = row0 + nlocal;
    float di = g_dinv[set][node];
    float2 acc = *reinterpret_cast<const float2*>(&x[node * 16 + 2 * f2]);
    float d2 = di * di;
    acc.x *= d2; acc.y *= d2;
    int beg = g_indptr[set][node], end = g_indptr[set][node + 1];
    const int2* ep = &g_epk[set][0];
    int i = beg;
    for (; i + 3 < end; i += 4) {
        int2 e0 = __ldg(&ep[i]);
        int2 e1 = __ldg(&ep[i + 1]);
        int2 e2 = __ldg(&ep[i + 2]);
        int2 e3 = __ldg(&ep[i + 3]);
        float2 u0 = *reinterpret_cast<const float2*>(&x[e0.x * 16 + 2 * f2]);
        float2 u1 = *reinterpret_cast<const float2*>(&x[e1.x * 16 + 2 * f2]);
        float2 u2 = *reinterpret_cast<const float2*>(&x[e2.x * 16 + 2 * f2]);
        float2 u3 = *reinterpret_cast<const float2*>(&x[e3.x * 16 + 2 * f2]);
        float w0 = __int_as_float(e0.y), w1 = __int_as_float(e1.y);
        float w2 = __int_as_float(e2.y), w3 = __int_as_float(e3.y);
        acc.x += w0 * u0.x + w1 * u1.x + w2 * u2.x + w3 * u3.x;
        acc.y += w0 * u0.y + w1 * u1.y + w2 * u2.y + w3 * u3.y;
    }
    for (; i < end; ++i) {
        int2 e0 = __ldg(&ep[i]);
        float2 u0 = *reinterpret_cast<const float2*>(&x[e0.x * 16 + 2 * f2]);
        float w0 = __int_as_float(e0.y);
        acc.x += w0 * u0.x; acc.y += w0 * u0.y;
    }
    Xs[nlocal * 16 + 2 * f2]     = acc.x;
    Xs[nlocal * 16 + 2 * f2 + 1] = acc.y;
    __syncthreads();

    float b = gcn_b[tid];
    #pragma unroll
    for (int r = 0; r < 16; ++r) {
        float a = b;
        #pragma unroll
        for (int f = 0; f < 16; ++f) a += Xs[r * 16 + f] * Ws[f * 128 + tid];
        a = fmaxf(a, 0.f);
        float vo = __shfl_xor_sync(0xffffffffu, a, 1);
        if (!(tid & 1)) {
            unsigned hi, lo;
            split_pk(a, vo, hi, lo);
            outh[(row0 + r) * 64 + (tid >> 1)] = hi;
            outl[(row0 + r) * 64 + (tid >> 1)] = lo;
        }
    }
}

__global__ void k_gcn_all(const float* __restrict__ x_seq,
                          const float* __restrict__ gcn_w,
                          const float* __restrict__ gcn_b) {
    int set = blockIdx.y;
    gcn_body(x_seq + (long long)set * NN * FF, set,
             &g_hg12h[set][0], &g_hg12l[set][0], gcn_w, gcn_b, blockIdx.x * 16);
}

// ---------------- single-launch R chain + bias + Wt pack ---------------------
__global__ void k_Rchain() {
    __shared__ float cur[2][128], prev[2][128];
    int b = blockIdx.x;
    int h = threadIdx.x;

    if (b == 64) {                       // bias recurrence
        __shared__ float b1[128], b2[128];
        float d = g_dvec[h];
        b1[h] = 0.f; b2[h] = 0.f;
        __syncthreads();
        for (int t = 0; t <= 11; ++t) {
            float acc = d;
            #pragma unroll 4
            for (int o = 0; o < 128; ++o)
                acc += b1[o] * g_W[(128 + o) * 128 + h] + b2[o] * g_W[o * 128 + h];
            __syncthreads();
            b2[h] = b1[h];
            b1[h] = acc;
            if (t == 10) g_bbig[0][h] = acc;
            if (t == 11) g_bbig[1][h] = acc;
            __syncthreads();
        }
        return;
    }

    int r0 = 2 * b;
    cur[0][h]  = g_W[(256 + r0) * 128 + h];       // R(0) = C
    cur[1][h]  = g_W[(256 + r0 + 1) * 128 + h];
    prev[0][h] = 0.f; prev[1][h] = 0.f;
    g_Wt_hi[0][(11 * 64 + b) * 128 + h] = 0u;
    g_Wt_lo[0][(11 * 64 + b) * 128 + h] = 0u;
    __syncthreads();

    for (int k = 0; k <= 11; ++k) {
        unsigned hi, lo;
        split_pk(cur[0][h], cur[1][h], hi, lo);
        if (k <= 10) {
            int s = 10 - k;
            g_Wt_hi[0][(s * 64 + b) * 128 + h] = hi;
            g_Wt_lo[0][(s * 64 + b) * 128 + h] = lo;
        }
        {
            int s = 11 - k;
            g_Wt_hi[1][(s * 64 + b) * 128 + h] = hi;
            g_Wt_lo[1][(s * 64 + b) * 128 + h] = lo;
        }
        if (k == 11) break;
        float a0 = 0.f, a1 = 0.f;
        #pragma unroll 4
        for (int o = 0; o < 128; ++o) {
            float Bv = g_W[(128 + o) * 128 + h];
            float Av = g_W[o * 128 + h];
            a0 += cur[0][o] * Bv + prev[0][o] * Av;
            a1 += cur[1][o] * Bv + prev[1][o] * Av;
        }
        __syncthreads();
        prev[0][h] = cur[0][h]; prev[1][h] = cur[1][h];
        __syncthreads();
        cur[0][h] = a0; cur[1][h] = a1;
        __syncthreads();
    }
}

// ---------------- MMA helper ---------------------------------------------
__device__ __forceinline__ void mma_bf16(float* c, const unsigned* a,
                                         unsigned b0, unsigned b1) {
    asm volatile(
        "mma.sync.aligned.m16n8k16.row.col.f32.bf16.bf16.f32 "
        "{%0,%1,%2,%3}, {%4,%5,%6,%7}, {%8,%9}, {%0,%1,%2,%3};"
        : "+f"(c[0]), "+f"(c[1]), "+f"(c[2]), "+f"(c[3])
        : "r"(a[0]), "r"(a[1]), "r"(a[2]), "r"(a[3]), "r"(b0), "r"(b1));
}

constexpr int ASTW = 12;   // A smem row stride in words (8 data + 4 pad)
constexpr int WST  = 136;  // W smem row stride in words

// ---------------- big encoder GEMM: h(10), h(11) in one launch ---------------
__global__ void __launch_bounds__(256, 2)
k_hbig() {
    __shared__ __align__(16) unsigned Ah[2][128 * ASTW];
    __shared__ __align__(16) unsigned Al[2][128 * ASTW];
    __shared__ __align__(16) unsigned Wh[2][8 * WST];
    __shared__ __align__(16) unsigned Wl[2][8 * WST];

    int tgt  = blockIdx.y;
    const unsigned* whp = g_Wt_hi[tgt];
    const unsigned* wlp = g_Wt_lo[tgt];

    int t    = threadIdx.x;
    int w    = t >> 5;
    int l    = t & 31;
    int row0 = blockIdx.x * 128;
    int wr   = w * 16;

    float acc[16][4];
    #pragma unroll
    for (int nt = 0; nt < 16; ++nt)
        #pragma unroll
        for (int j = 0; j < 4; ++j) acc[nt][j] = 0.f;

    int arow = t >> 1, ahalf = t & 1;
    int wkk  = t >> 5, wns = l * 4;
    long long agi = (long long)(row0 + arow) * 64 + ahalf * 4;
    bool arow_ok = (row0 + arow) < NN;

    {
        uint4 uh = {0,0,0,0}, ul = {0,0,0,0};
        if (arow_ok) {
            uh = __ldg(reinterpret_cast<const uint4*>(&g_hg12h[0][0] + agi));
            ul = __ldg(reinterpret_cast<const uint4*>(&g_hg12l[0][0] + agi));
        }
        *reinterpret_cast<uint4*>(&Ah[0][arow * ASTW + ahalf * 4]) = uh;
        *reinterpret_cast<uint4*>(&Al[0][arow * ASTW + ahalf * 4]) = ul;
        uint4 pwh = __ldg(reinterpret_cast<const uint4*>(&whp[wkk * 128 + wns]));
        uint4 pwl = __ldg(reinterpret_cast<const uint4*>(&wlp[wkk * 128 + wns]));
        *reinterpret_cast<uint4*>(&Wh[0][wkk * WST + wns]) = pwh;
        *reinterpret_cast<uint4*>(&Wl[0][wkk * WST + wns]) = pwl;
    }
    __syncthreads();

    int rb = wr + (l >> 2);
    int kw = l & 3;

    #pragma unroll 1
    for (int c = 0; c < 96; ++c) {
        int buf = c & 1;
        bool has = (c + 1 < 96);

        uint4 uh = {0,0,0,0}, ul = {0,0,0,0}, pwh, pwl;
        if (has) {
            int cn = c + 1;
            const unsigned* sh_ = &g_hg12h[cn >> 3][0];
            const unsigned* sl_ = &g_hg12l[cn >> 3][0];
            if (arow_ok) {
                uh = __ldg(reinterpret_cast<const uint4*>(sh_ + agi + (cn & 7) * 8));
                ul = __ldg(reinterpret_cast<const uint4*>(sl_ + agi + (cn & 7) * 8));
            }
            pwh = __ldg(reinterpret_cast<const uint4*>(&whp[(cn * 8 + wkk) * 128 + wns]));
            pwl = __ldg(reinterpret_cast<const uint4*>(&wlp[(cn * 8 + wkk) * 128 + wns]));
        }

        const unsigned* ah = &Ah[buf][0];
        const unsigned* al = &Al[buf][0];
        unsigned ahi[4], alo[4];
        ahi[0] = ah[rb * ASTW + kw];
        ahi[1] = ah[(rb + 8) * ASTW + kw];
        ahi[2] = ah[rb * ASTW + 4 + kw];
        ahi[3] = ah[(rb + 8) * ASTW + 4 + kw];
        alo[0] = al[rb * ASTW + kw];
        alo[1] = al[(rb + 8) * ASTW + kw];
        alo[2] = al[rb * ASTW + 4 + kw];
        alo[3] = al[(rb + 8) * ASTW + 4 + kw];
        #pragma unroll
        for (int nt = 0; nt < 16; ++nt) {
            int wb = nt * 8 + (l >> 2);
            unsigned bh0 = Wh[buf][kw * WST + wb];
            unsigned bh1 = Wh[buf][(4 + kw) * WST + wb];
            unsigned bl0 = Wl[buf][kw * WST + wb];
            unsigned bl1 = Wl[buf][(4 + kw) * WST + wb];
            mma_bf16(acc[nt], ahi, bh0, bh1);
            mma_bf16(acc[nt], ahi, bl0, bl1);
            mma_bf16(acc[nt], alo, bh0, bh1);
        }

        if (has) {
            int nbuf = buf ^ 1;
            *reinterpret_cast<uint4*>(&Ah[nbuf][arow * ASTW + ahalf * 4]) = uh;
            *reinterpret_cast<uint4*>(&Al[nbuf][arow * ASTW + ahalf * 4]) = ul;
            *reinterpret_cast<uint4*>(&Wh[nbuf][wkk * WST + wns]) = pwh;
            *reinterpret_cast<uint4*>(&Wl[nbuf][wkk * WST + wns]) = pwl;
        }
        __syncthreads();
    }

    unsigned* dsth = g_hbh[tgt];
    unsigned* dstl = g_hbl[tgt];
    const float* bb = g_bbig[tgt];
    int cw = 2 * (l & 3);
    int rA = row0 + rb;
    #pragma unroll
    for (int nt = 0; nt < 16; ++nt) {
        int col = nt * 8 + cw;
        float2 dv = *reinterpret_cast<const float2*>(&bb[col]);
        unsigned hi, lo;
        if (rA < NN) {
            split_pk(acc[nt][0] + dv.x, acc[nt][1] + dv.y, hi, lo);
            dsth[(long long)rA * 64 + col / 2] = hi;
            dstl[(long long)rA * 64 + col / 2] = lo;
        }
        if (rA + 8 < NN) {
            split_pk(acc[nt][2] + dv.x, acc[nt][3] + dv.y, hi, lo);
            dsth[(long long)(rA + 8) * 64 + col / 2] = hi;
            dstl[(long long)(rA + 8) * 64 + col / 2] = lo;
        }
    }
}

// ---------------- persistent cooperative decoder ------------------------------
// ONE launch: 6 x { hnew GEMM + y head -> grid.sync -> feedback GCN -> sync }
constexpr int DEC_BLOCKS = 157;

__global__ void __launch_bounds__(256, 2)
k_decoder(const float* __restrict__ gcn_w, const float* __restrict__ gcn_b,
          const float* __restrict__ head_w, const float* __restrict__ head_b,
          float* __restrict__ out) {
    cg::grid_group grid = cg::this_grid();

    // aliased smem: hnew phase needs 33280 B; gcn phase needs 10240 B
    __shared__ __align__(16) unsigned char sraw[2 * 128 * ASTW * 4 * 2 +
                                                2 * 8 * WST * 4 * 2];
    unsigned (*Ah)[128 * ASTW] = reinterpret_cast<unsigned(*)[128 * ASTW]>(sraw);
    unsigned (*Al)[128 * ASTW] =
        reinterpret_cast<unsigned(*)[128 * ASTW]>(sraw + 2 * 128 * ASTW * 4);
    unsigned (*Wh)[8 * WST] =
        reinterpret_cast<unsigned(*)[8 * WST]>(sraw + 4 * 128 * ASTW * 4);
    unsigned (*Wl)[8 * WST] =
        reinterpret_cast<unsigned(*)[8 * WST]>(sraw + 4 * 128 * ASTW * 4 +
                                               2 * 8 * WST * 4);

    int t    = threadIdx.x;
    int w    = t >> 5;
    int l    = t & 31;
    int row0 = blockIdx.x * 128;
    int wr   = w * 16;
    int arow = t >> 1, ahalf = t & 1;
    int wkk  = t >> 5, wns = l * 4;
    long long agi = (long long)(row0 + arow) * 64 + ahalf * 4;
    bool arow_ok = (row0 + arow) < NN;
    int rb = wr + (l >> 2);
    int kw = l & 3;
    int cw = 2 * (l & 3);
    int rA = row0 + rb;

    int i1 = 0, i2 = 1, idst = 2;

    for (int it = 0; it < HOR; ++it) {
        const unsigned* hgh = (it == 0) ? &g_hg12h[TT - 1][0] : g_aggh;
        const unsigned* hgl = (it == 0) ? &g_hg12l[TT - 1][0] : g_aggl;
        const unsigned* h1h = g_hbh[i1];
        const unsigned* h1l = g_hbl[i1];
        const unsigned* h2h = g_hbh[i2];
        const unsigned* h2l = g_hbl[i2];
        float* outy = out + (long long)it * NN * CC;

        float acc[16][4];
        #pragma unroll
        for (int nt = 0; nt < 16; ++nt)
            #pragma unroll
            for (int j = 0; j < 4; ++j) acc[nt][j] = 0.f;

        {
            uint4 uh = {0,0,0,0}, ul = {0,0,0,0};
            if (arow_ok) {
                uh = __ldg(reinterpret_cast<const uint4*>(h1h + agi));
                ul = __ldg(reinterpret_cast<const uint4*>(h1l + agi));
            }
            *reinterpret_cast<uint4*>(&Ah[0][arow * ASTW + ahalf * 4]) = uh;
            *reinterpret_cast<uint4*>(&Al[0][arow * ASTW + ahalf * 4]) = ul;
            uint4 pwh = __ldg(reinterpret_cast<const uint4*>(&g_Whi_pk[wkk * 128 + wns]));
            uint4 pwl = __ldg(reinterpret_cast<const uint4*>(&g_Wlo_pk[wkk * 128 + wns]));
            *reinterpret_cast<uint4*>(&Wh[0][wkk * WST + wns]) = pwh;
            *reinterpret_cast<uint4*>(&Wl[0][wkk * WST + wns]) = pwl;
        }
        __syncthreads();

        for (int c = 0; c < 24; ++c) {
            int buf = c & 1;
            bool has = (c + 1 < 24);

            uint4 uh = {0,0,0,0}, ul = {0,0,0,0}, pwh, pwl;
            if (has) {
                int cn = c + 1;
                const unsigned* sh_ = (cn < 8) ? h1h : (cn < 16) ? h2h : hgh;
                const unsigned* sl_ = (cn < 8) ? h1l : (cn < 16) ? h2l : hgl;
                if (arow_ok) {
                    uh = __ldg(reinterpret_cast<const uint4*>(sh_ + agi + (cn & 7) * 8));
                    ul = __ldg(reinterpret_cast<const uint4*>(sl_ + agi + (cn & 7) * 8));
                }
                pwh = __ldg(reinterpret_cast<const uint4*>(&g_Whi_pk[(cn * 8 + wkk) * 128 + wns]));
                pwl = __ldg(reinterpret_cast<const uint4*>(&g_Wlo_pk[(cn * 8 + wkk) * 128 + wns]));
            }

            const unsigned* ah = &Ah[buf][0];
            const unsigned* al = &Al[buf][0];
            unsigned ahi[4], alo[4];
            ahi[0] = ah[rb * ASTW + kw];
            ahi[1] = ah[(rb + 8) * ASTW + kw];
            ahi[2] = ah[rb * ASTW + 4 + kw];
            ahi[3] = ah[(rb + 8) * ASTW + 4 + kw];
            alo[0] = al[rb * ASTW + kw];
            alo[1] = al[(rb + 8) * ASTW + kw];
            alo[2] = al[rb * ASTW + 4 + kw];
            alo[3] = al[(rb + 8) * ASTW + 4 + kw];
            #pragma unroll
            for (int nt = 0; nt < 16; ++nt) {
                int wb = nt * 8 + (l >> 2);
                unsigned bh0 = Wh[buf][kw * WST + wb];
                unsigned bh1 = Wh[buf][(4 + kw) * WST + wb];
                unsigned bl0 = Wl[buf][kw * WST + wb];
                unsigned bl1 = Wl[buf][(4 + kw) * WST + wb];
                mma_bf16(acc[nt], ahi, bh0, bh1);
                mma_bf16(acc[nt], ahi, bl0, bl1);
                mma_bf16(acc[nt], alo, bh0, bh1);
            }

            if (has) {
                int nbuf = buf ^ 1;
                *reinterpret_cast<uint4*>(&Ah[nbuf][arow * ASTW + ahalf * 4]) = uh;
                *reinterpret_cast<uint4*>(&Al[nbuf][arow * ASTW + ahalf * 4]) = ul;
                *reinterpret_cast<uint4*>(&Wh[nbuf][wkk * WST + wns]) = pwh;
                *reinterpret_cast<uint4*>(&Wl[nbuf][wkk * WST + wns]) = pwl;
            }
            __syncthreads();
        }

        // epilogue: bias; store packed bf16 hi/lo; fused y head
        unsigned* dsth = g_hbh[idst];
        unsigned* dstl = g_hbl[idst];
        #pragma unroll
        for (int nt = 0; nt < 16; ++nt) {
            int col = nt * 8 + cw;
            float2 dv = *reinterpret_cast<const float2*>(&g_dvec[col]);
            acc[nt][0] += dv.x; acc[nt][1] += dv.y;
            acc[nt][2] += dv.x; acc[nt][3] += dv.y;
            unsigned hi, lo;
            if (rA < NN) {
                split_pk(acc[nt][0], acc[nt][1], hi, lo);
                dsth[(long long)rA * 64 + col / 2] = hi;
                dstl[(long long)rA * 64 + col / 2] = lo;
            }
            if (rA + 8 < NN) {
                split_pk(acc[nt][2], acc[nt][3], hi, lo);
                dsth[(long long)(rA + 8) * 64 + col / 2] = hi;
                dstl[(long long)(rA + 8) * 64 + col / 2] = lo;
            }
        }

        {
            float* Hw = reinterpret_cast<float*>(&Ah[0][0]);
            for (int i = t; i < 16 * 128; i += 256) Hw[i] = head_w[i];
            __syncthreads();
            #pragma unroll
            for (int ch = 0; ch < 16; ++ch) {
                float s0 = 0.f, s1 = 0.f;
                #pragma unroll
                for (int nt = 0; nt < 16; ++nt) {
                    int col = nt * 8 + cw;
                    float w0 = Hw[ch * 128 + col], w1 = Hw[ch * 128 + col + 1];
                    s0 += acc[nt][0] * w0 + acc[nt][1] * w1;
                    s1 += acc[nt][2] * w0 + acc[nt][3] * w1;
                }
                s0 += __shfl_xor_sync(0xffffffffu, s0, 1);
                s0 += __shfl_xor_sync(0xffffffffu, s0, 2);
                s1 += __shfl_xor_sync(0xffffffffu, s1, 1);
                s1 += __shfl_xor_sync(0xffffffffu, s1, 2);
                if ((l & 3) == 0) {
                    float hb = __ldg(&head_b[ch]);
                    if (rA < NN)     outy[(long long)rA * 16 + ch] = s0 + hb;
                    if (rA + 8 < NN) outy[(long long)(rA + 8) * 16 + ch] = s1 + hb;
                }
            }
        }

        grid.sync();

        // feedback GCN for next step (32 nodes per tile, 625 tiles)
        if (it + 1 < HOR) {
            const float* xin = outy;
            float* Xs = reinterpret_cast<float*>(sraw);                 // 32x16
            float* Ws = reinterpret_cast<float*>(sraw + 32 * 16 * 4);   // 16x128
            int col = t & 127;
            for (int i = t; i < 16 * 128; i += 256)
                Ws[i] = gcn_w[i];

            int nl8  = (t >> 5) * 4 + ((t & 31) >> 3);  // 0..31
            int f2   = t & 7;                            // via lane&7
            f2 = (t & 31) & 7;
            const int2* ep = &g_epk[TT - 1][0];
            for (int vb = blockIdx.x; vb < 625; vb += gridDim.x) {
                int nrow0 = vb * 32;
                int node  = nrow0 + nl8;
                float di = g_dinv[TT - 1][node];
                float2 acc2 = *reinterpret_cast<const float2*>(&xin[node * 16 + 2 * f2]);
                float d2 = di * di;
                acc2.x *= d2; acc2.y *= d2;
                int beg = g_indptr[TT - 1][node], end = g_indptr[TT - 1][node + 1];
                int i = beg;
                for (; i + 3 < end; i += 4) {
                    int2 e0 = __ldg(&ep[i]);
                    int2 e1 = __ldg(&ep[i + 1]);
                    int2 e2 = __ldg(&ep[i + 2]);
                    int2 e3 = __ldg(&ep[i + 3]);
                    float2 u0 = *reinterpret_cast<const float2*>(&xin[e0.x * 16 + 2 * f2]);
                    float2 u1 = *reinterpret_cast<const float2*>(&xin[e1.x * 16 + 2 * f2]);
                    float2 u2 = *reinterpret_cast<const float2*>(&xin[e2.x * 16 + 2 * f2]);
                    float2 u3 = *reinterpret_cast<const float2*>(&xin[e3.x * 16 + 2 * f2]);
                    float w0 = __int_as_float(e0.y), w1 = __int_as_float(e1.y);
                    float w2 = __int_as_float(e2.y), w3 = __int_as_float(e3.y);
                    acc2.x += w0 * u0.x + w1 * u1.x + w2 * u2.x + w3 * u3.x;
                    acc2.y += w0 * u0.y + w1 * u1.y + w2 * u2.y + w3 * u3.y;
                }
                for (; i < end; ++i) {
                    int2 e0 = __ldg(&ep[i]);
                    float2 u0 = *reinterpret_cast<const float2*>(&xin[e0.x * 16 + 2 * f2]);
                    float w0 = __int_as_float(e0.y);
                    acc2.x += w0 * u0.x; acc2.y += w0 * u0.y;
                }
                __syncthreads();   // Xs may still be read by previous vb iter
                Xs[nl8 * 16 + 2 * f2]     = acc2.x;
                Xs[nl8 * 16 + 2 * f2 + 1] = acc2.y;
                __syncthreads();

                // weight multiply: threads 0-127 -> nodes 0-15, 128-255 -> 16-31
                int rbase = (t >> 7) * 16;
                float b = gcn_b[col];
                #pragma unroll
                for (int r = 0; r < 16; ++r) {
                    float a = b;
                    #pragma unroll
                    for (int f = 0; f < 16; ++f)
                        a += Xs[(rbase + r) * 16 + f] * Ws[f * 128 + col];
                    a = fmaxf(a, 0.f);
                    float vo = __shfl_xor_sync(0xffffffffu, a, 1);
                    if (!(t & 1)) {
                        unsigned hi, lo;
                        split_pk(a, vo, hi, lo);
                        int gnode = nrow0 + rbase + r;
                        g_aggh[gnode * 64 + (col >> 1)] = hi;
                        g_aggl[gnode * 64 + (col >> 1)] = lo;
                    }
                }
            }
        }

        grid.sync();

        int old1 = i1; i1 = i2; i2 = idst; idst = old1;
    }
}

// ---------------------------------------------------------------------------
extern "C" void kernel_launch(void* const* d_in, const int* in_sizes, int n_in,
                              void* d_out, int out_size) {
    const float* x_seq  = (const float*)d_in[0];
    const void*  ei     = d_in[1];
    const float* gcn_w  = (const float*)d_in[5];
    const float* gcn_b  = (const float*)d_in[6];
    const float* conv_w = (const float*)d_in[7];
    const float* conv_b = (const float*)d_in[8];
    const float* proj_w = (const float*)d_in[9];
    const float* proj_b = (const float*)d_in[10];
    const float* head_w = (const float*)d_in[11];
    const float* head_b = (const float*)d_in[12];
    float* out = (float*)d_out;

    // prep + CSR
    k_init<<<(TT * NN + 255) / 256, 256>>>((const unsigned*)ei);
    k_prepWsd<<<193, 128>>>(conv_w, proj_w, conv_b, proj_b);
    {
        long long tot = (long long)TT * EE;
        int blocks = (int)((tot + 255) / 256);
        k_count12<<<blocks, 256>>>(ei);
        k_scanA<<<dim3(10, TT), 256>>>();
        k_scanB<<<dim3(10, TT), 256>>>();
        k_fill12<<<blocks, 256>>>(ei);
    }

    // all 12 encoder GCNs
    {
        dim3 gg(NN / 16, TT);
        k_gcn_all<<<gg, 128>>>(x_seq, gcn_w, gcn_b);
    }

    // transfer-matrix chain + biases + Wt pack — ONE launch
    k_Rchain<<<65, 128>>>();

    // one wide GEMM: h(10) -> buffer 0, h(11) -> buffer 1
    k_hbig<<<dim3((NN + 127) / 128, 2), 256>>>();

    // entire decoder in ONE cooperative launch
    {
        void* args[] = { (void*)&gcn_w, (void*)&gcn_b, (void*)&head_w,
                         (void*)&head_b, (void*)&out };
        cudaLaunchCooperativeKernel((void*)k_decoder, dim3(DEC_BLOCKS),
                                    dim3(256), args, 0, 0);
    }
}

// round 15
// speedup vs baseline: 1.1305x; 1.1305x over previous
#include <cuda_runtime.h>
#include <cuda_bf16.h>

constexpr int NN  = 20000;   // nodes
constexpr int TT  = 12;      // encoder steps
constexpr int HOR = 6;       // decoder horizon
constexpr int FF  = 16;      // input features (== C, decoder feedback)
constexpr int EE  = 320000;  // edges
constexpr int HH  = 128;     // hidden
constexpr int CC  = 16;      // out channels

// ---------------- scratch (static device globals; no allocation) -----------
__device__ __align__(16) float g_W[384 * HH];         // fused [A;B;C] fp32
__device__ __align__(16) float g_dvec[HH];            // fused bias vector
__device__ __align__(16) unsigned g_Whi_pk[192 * HH]; // bf16x2-packed hi(W)
__device__ __align__(16) unsigned g_Wlo_pk[192 * HH]; // bf16x2-packed lo(W)

// big encoder weight (packed directly by k_Rchain) and biases
__device__ __align__(16) float g_bbig[2][HH];         // bias(10), bias(11)
__device__ __align__(16) unsigned g_Wt_hi[2][768 * HH];
__device__ __align__(16) unsigned g_Wt_lo[2][768 * HH];

// pre-packed bf16 hi/lo activations
__device__ __align__(16) unsigned g_hg12h[TT][NN * 64];
__device__ __align__(16) unsigned g_hg12l[TT][NN * 64];
__device__ __align__(16) unsigned g_hbh[3][NN * 64];
__device__ __align__(16) unsigned g_hbl[3][NN * 64];
__device__ __align__(16) unsigned g_aggh[NN * 64];
__device__ __align__(16) unsigned g_aggl[NN * 64];
__device__ int   g_is64;

// per-edge-set CSR (built once per launch)
__device__ int   g_deg[TT][NN];
__device__ int   g_indptr[TT][NN + 1];
__device__ int   g_cur[TT][NN];
__device__ float g_dinv[TT][NN];
__device__ __align__(8) int2 g_epk[TT][EE];           // packed (src, w_bits)
__device__ int   g_psum[TT][10];

// ---------------- helpers ----------------------------------------------------
__device__ __forceinline__ unsigned pk_bf(__nv_bfloat16 a, __nv_bfloat16 b) {
    __nv_bfloat162 x; x.x = a; x.y = b;
    return *reinterpret_cast<unsigned*>(&x);
}
__device__ __forceinline__ void split_pk(float a, float b,
                                         unsigned& hi, unsigned& lo) {
    __nv_bfloat16 ha = __float2bfloat16(a);
    __nv_bfloat16 hb = __float2bfloat16(b);
    __nv_bfloat16 la = __float2bfloat16(a - __bfloat162float(ha));
    __nv_bfloat16 lb = __float2bfloat16(b - __bfloat162float(hb));
    hi = pk_bf(ha, hb);
    lo = pk_bf(la, lb);
}

__device__ __forceinline__ int load_idx(const void* p, long long e) {
    int v;
    if (g_is64) v = (int)((const long long*)p)[e];
    else        v = ((const int*)p)[e];
    v = v < 0 ? 0 : (v >= NN ? NN - 1 : v);
    return v;
}

// ---------------- detect dtype + zero degree arrays --------------------------
__global__ void k_init(const unsigned* __restrict__ w) {
    long long idx = (long long)blockIdx.x * blockDim.x + threadIdx.x;
    if (idx < (long long)TT * NN) (&g_deg[0][0])[idx] = 0;
    if (idx == 0) {
        int nz = 0;
        #pragma unroll 8
        for (int i = 0; i < 128; ++i) nz += (w[2 * i + 1] != 0u);
        g_is64 = (nz == 0) ? 1 : 0;
    }
}

// ---------------- fold conv/proj -> W (fp32 + bf16 split), dvec --------------
__global__ void k_prepWsd(const float* __restrict__ conv_w,
                          const float* __restrict__ proj_w,
                          const float* __restrict__ conv_b,
                          const float* __restrict__ proj_b) {
    int h = threadIdx.x;
    if (blockIdx.x == 192) {             // dvec
        float acc = proj_b[h];
        #pragma unroll 4
        for (int j = 0; j < 384; ++j) acc += conv_b[j] * proj_w[h * 384 + j];
        g_dvec[h] = acc;
        return;
    }
    __shared__ float wa[6][128];
    int kp = blockIdx.x;                 // 0..191
    int c0 = 2 * kp, c1 = c0 + 1;
    float a0 = 0.f, a1 = 0.f;
    if (c0 < 128) {
        wa[0][h] = conv_w[((128 + h) * 128 + c0) * 3 + 0];
        wa[1][h] = conv_w[((128 + h) * 128 + c1) * 3 + 0];
        __syncthreads();
        #pragma unroll 4
        for (int o = 0; o < 128; ++o) {
            float p = proj_w[h * 384 + 128 + o];
            a0 += wa[0][o] * p; a1 += wa[1][o] * p;
        }
    } else if (c0 < 256) {
        int cc0 = c0 - 128, cc1 = c1 - 128;
        wa[0][h] = conv_w[(h * 128 + cc0) * 3 + 0];
        wa[1][h] = conv_w[(h * 128 + cc1) * 3 + 0];
        __syncthreads();
        #pragma unroll 4
        for (int o = 0; o < 128; ++o) {
            float p = proj_w[h * 384 + o];
            a0 += wa[0][o] * p; a1 += wa[1][o] * p;
        }
    } else {
        int cc0 = c0 - 256, cc1 = c1 - 256;
        wa[0][h] = conv_w[(h * 128 + cc0) * 3 + 1];
        wa[1][h] = conv_w[((128 + h) * 128 + cc0) * 3 + 1];
        wa[2][h] = conv_w[((256 + h) * 128 + cc0) * 3 + 1];
        wa[3][h] = conv_w[(h * 128 + cc1) * 3 + 1];
        wa[4][h] = conv_w[((128 + h) * 128 + cc1) * 3 + 1];
        wa[5][h] = conv_w[((256 + h) * 128 + cc1) * 3 + 1];
        __syncthreads();
        #pragma unroll 2
        for (int o = 0; o < 128; ++o) {
            float p0 = proj_w[h * 384 + o];
            float p1 = proj_w[h * 384 + 128 + o];
            float p2 = proj_w[h * 384 + 256 + o];
            a0 += wa[0][o] * p0 + wa[1][o] * p1 + wa[2][o] * p2;
            a1 += wa[3][o] * p0 + wa[4][o] * p1 + wa[5][o] * p2;
        }
    }
    g_W[c0 * 128 + h] = a0;
    g_W[c1 * 128 + h] = a1;
    unsigned hi, lo;
    split_pk(a0, a1, hi, lo);
    g_Whi_pk[kp * 128 + h] = hi;
    g_Wlo_pk[kp * 128 + h] = lo;
}

// ---------------- CSR construction ----------------------------------------
__global__ void k_count12(const void* __restrict__ ei) {
    long long idx = (long long)blockIdx.x * blockDim.x + threadIdx.x;
    if (idx >= (long long)TT * EE) return;
    int set = (int)(idx / EE);
    int e   = (int)(idx % EE);
    int d = load_idx(ei, (long long)set * 2 * EE + EE + e);
    atomicAdd(&g_deg[set][d], 1);
}

__global__ void k_scanA() {
    __shared__ int wsum[8];
    int set = blockIdx.y, chunk = blockIdx.x;
    int t = threadIdx.x, lane = t & 31, wid = t >> 5;
    int base = chunk * 2000;
    int acc = 0;
    for (int j = t; j < 2000; j += 256) acc += g_deg[set][base + j];
    #pragma unroll
    for (int d = 16; d > 0; d >>= 1) acc += __shfl_down_sync(~0u, acc, d);
    if (lane == 0) wsum[wid] = acc;
    __syncthreads();
    if (t == 0) {
        int s = 0;
        #pragma unroll
        for (int w = 0; w < 8; ++w) s += wsum[w];
        g_psum[set][chunk] = s;
    }
}

__global__ void k_scanB() {
    __shared__ int sm[2048];
    __shared__ int woff[8];
    __shared__ int s_off;
    int set = blockIdx.y, chunk = blockIdx.x;
    int t = threadIdx.x, lane = t & 31, wid = t >> 5;
    int base = chunk * 2000;
    if (t == 0) {
        int o = 0;
        for (int c = 0; c < chunk; ++c) o += g_psum[set][c];
        s_off = o;
    }
    for (int j = t; j < 2048; j += 256)
        sm[j] = (j < 2000) ? g_deg[set][base + j] : 0;
    __syncthreads();
    int v[8];
    int run = 0;
    #pragma unroll
    for (int i = 0; i < 8; ++i) { v[i] = sm[t * 8 + i]; run += v[i]; }
    int x = run;
    #pragma unroll
    for (int d = 1; d < 32; d <<= 1) {
        int y = __shfl_up_sync(~0u, x, d);
        if (lane >= d) x += y;
    }
    if (lane == 31) woff[wid] = x;
    __syncthreads();
    if (t == 0) {
        int o = 0;
        #pragma unroll
        for (int w = 0; w < 8; ++w) { int tmp = woff[w]; woff[w] = o; o += tmp; }
    }
    __syncthreads();
    int runp = s_off + woff[wid] + (x - run);
    #pragma unroll
    for (int i = 0; i < 8; ++i) {
        int j = t * 8 + i;
        if (j < 2000) {
            int n = base + j;
            g_indptr[set][n] = runp;
            g_cur[set][n]    = runp;
            g_dinv[set][n]   = rsqrtf(1.0f + (float)v[i]);
            runp += v[i];
        }
    }
    if (chunk == 9 && t == 249) g_indptr[set][NN] = runp;
}

__global__ void k_fill12(const void* __restrict__ ei) {
    long long idx = (long long)blockIdx.x * blockDim.x + threadIdx.x;
    if (idx >= (long long)TT * EE) return;
    int set = (int)(idx / EE);
    int e   = (int)(idx % EE);
    long long b = (long long)set * 2 * EE;
    int s = load_idx(ei, b + e);
    int d = load_idx(ei, b + EE + e);
    int pos = atomicAdd(&g_cur[set][d], 1);
    float w = g_dinv[set][s] * g_dinv[set][d];
    g_epk[set][pos] = make_int2(s, __float_as_int(w));
}

// ---------------- fused GCN: aggregate -> weight multiply -> split+pack ------
__device__ __forceinline__ void gcn_body(const float* __restrict__ x, int set,
                                         unsigned* __restrict__ outh,
                                         unsigned* __restrict__ outl,
                                         const float* __restrict__ gcn_w,
                                         const float* __restrict__ gcn_b,
                                         int row0) {
    __shared__ float Xs[16 * 16];
    __shared__ float Ws[16 * 128];
    int tid = threadIdx.x;
    #pragma unroll
    for (int i = 0; i < 16; ++i) Ws[i * 128 + tid] = gcn_w[i * 128 + tid];

    int lane   = tid & 31;
    int nlocal = (tid >> 5) * 4 + (lane >> 3);
    int f2     = lane & 7;
    int node   = row0 + nlocal;
    float di = g_dinv[set][node];
    float2 acc = *reinterpret_cast<const float2*>(&x[node * 16 + 2 * f2]);
    float d2 = di * di;
    acc.x *= d2; acc.y *= d2;
    int beg = g_indptr[set][node], end = g_indptr[set][node + 1];
    const int2* ep = &g_epk[set][0];
    int i = beg;
    for (; i + 3 < end; i += 4) {
        int2 e0 = __ldg(&ep[i]);
        int2 e1 = __ldg(&ep[i + 1]);
        int2 e2 = __ldg(&ep[i + 2]);
        int2 e3 = __ldg(&ep[i + 3]);
        float2 u0 = *reinterpret_cast<const float2*>(&x[e0.x * 16 + 2 * f2]);
        float2 u1 = *reinterpret_cast<const float2*>(&x[e1.x * 16 + 2 * f2]);
        float2 u2 = *reinterpret_cast<const float2*>(&x[e2.x * 16 + 2 * f2]);
        float2 u3 = *reinterpret_cast<const float2*>(&x[e3.x * 16 + 2 * f2]);
        float w0 = __int_as_float(e0.y), w1 = __int_as_float(e1.y);
        float w2 = __int_as_float(e2.y), w3 = __int_as_float(e3.y);
        acc.x += w0 * u0.x + w1 * u1.x + w2 * u2.x + w3 * u3.x;
        acc.y += w0 * u0.y + w1 * u1.y + w2 * u2.y + w3 * u3.y;
    }
    for (; i < end; ++i) {
        int2 e0 = __ldg(&ep[i]);
        float2 u0 = *reinterpret_cast<const float2*>(&x[e0.x * 16 + 2 * f2]);
        float w0 = __int_as_float(e0.y);
        acc.x += w0 * u0.x; acc.y += w0 * u0.y;
    }
    Xs[nlocal * 16 + 2 * f2]     = acc.x;
    Xs[nlocal * 16 + 2 * f2 + 1] = acc.y;
    __syncthreads();

    float b = gcn_b[tid];
    #pragma unroll
    for (int r = 0; r < 16; ++r) {
        float a = b;
        #pragma unroll
        for (int f = 0; f < 16; ++f) a += Xs[r * 16 + f] * Ws[f * 128 + tid];
        a = fmaxf(a, 0.f);
        float vo = __shfl_xor_sync(0xffffffffu, a, 1);
        if (!(tid & 1)) {
            unsigned hi, lo;
            split_pk(a, vo, hi, lo);
            outh[(row0 + r) * 64 + (tid >> 1)] = hi;
            outl[(row0 + r) * 64 + (tid >> 1)] = lo;
        }
    }
}

__global__ void k_gcn_all(const float* __restrict__ x_seq,
                          const float* __restrict__ gcn_w,
                          const float* __restrict__ gcn_b) {
    int set = blockIdx.y;
    gcn_body(x_seq + (long long)set * NN * FF, set,
             &g_hg12h[set][0], &g_hg12l[set][0], gcn_w, gcn_b, blockIdx.x * 16);
}

__global__ void k_gcn1(const float* __restrict__ x,
                       const float* __restrict__ gcn_w,
                       const float* __restrict__ gcn_b) {
    gcn_body(x, TT - 1, g_aggh, g_aggl, gcn_w, gcn_b, blockIdx.x * 16);
}

// ---------------- single-launch R chain + bias + Wt pack ---------------------
__global__ void k_Rchain() {
    __shared__ float cur[2][128], prev[2][128];
    int b = blockIdx.x;
    int h = threadIdx.x;

    if (b == 64) {                       // bias recurrence
        __shared__ float b1[128], b2[128];
        float d = g_dvec[h];
        b1[h] = 0.f; b2[h] = 0.f;
        __syncthreads();
        for (int t = 0; t <= 11; ++t) {
            float acc = d;
            #pragma unroll 4
            for (int o = 0; o < 128; ++o)
                acc += b1[o] * g_W[(128 + o) * 128 + h] + b2[o] * g_W[o * 128 + h];
            __syncthreads();
            b2[h] = b1[h];
            b1[h] = acc;
            if (t == 10) g_bbig[0][h] = acc;
            if (t == 11) g_bbig[1][h] = acc;
            __syncthreads();
        }
        return;
    }

    int r0 = 2 * b;
    cur[0][h]  = g_W[(256 + r0) * 128 + h];       // R(0) = C
    cur[1][h]  = g_W[(256 + r0 + 1) * 128 + h];
    prev[0][h] = 0.f; prev[1][h] = 0.f;
    g_Wt_hi[0][(11 * 64 + b) * 128 + h] = 0u;
    g_Wt_lo[0][(11 * 64 + b) * 128 + h] = 0u;
    __syncthreads();

    for (int k = 0; k <= 11; ++k) {
        unsigned hi, lo;
        split_pk(cur[0][h], cur[1][h], hi, lo);
        if (k <= 10) {
            int s = 10 - k;
            g_Wt_hi[0][(s * 64 + b) * 128 + h] = hi;
            g_Wt_lo[0][(s * 64 + b) * 128 + h] = lo;
        }
        {
            int s = 11 - k;
            g_Wt_hi[1][(s * 64 + b) * 128 + h] = hi;
            g_Wt_lo[1][(s * 64 + b) * 128 + h] = lo;
        }
        if (k == 11) break;
        float a0 = 0.f, a1 = 0.f;
        #pragma unroll 4
        for (int o = 0; o < 128; ++o) {
            float Bv = g_W[(128 + o) * 128 + h];
            float Av = g_W[o * 128 + h];
            a0 += cur[0][o] * Bv + prev[0][o] * Av;
            a1 += cur[1][o] * Bv + prev[1][o] * Av;
        }
        __syncthreads();
        prev[0][h] = cur[0][h]; prev[1][h] = cur[1][h];
        __syncthreads();
        cur[0][h] = a0; cur[1][h] = a1;
        __syncthreads();
    }
}

// ---------------- MMA helper ---------------------------------------------
__device__ __forceinline__ void mma_bf16(float* c, const unsigned* a,
                                         unsigned b0, unsigned b1) {
    asm volatile(
        "mma.sync.aligned.m16n8k16.row.col.f32.bf16.bf16.f32 "
        "{%0,%1,%2,%3}, {%4,%5,%6,%7}, {%8,%9}, {%0,%1,%2,%3};"
        : "+f"(c[0]), "+f"(c[1]), "+f"(c[2]), "+f"(c[3])
        : "r"(a[0]), "r"(a[1]), "r"(a[2]), "r"(a[3]), "r"(b0), "r"(b1));
}

constexpr int ASTW = 12;   // A smem row stride in words (8 data + 4 pad)
constexpr int WST  = 136;  // W smem row stride in words

// ---------------- big encoder GEMM: h(10), h(11) in one launch ---------------
__global__ void __launch_bounds__(256, 2)
k_hbig() {
    __shared__ __align__(16) unsigned Ah[2][128 * ASTW];
    __shared__ __align__(16) unsigned Al[2][128 * ASTW];
    __shared__ __align__(16) unsigned Wh[2][8 * WST];
    __shared__ __align__(16) unsigned Wl[2][8 * WST];

    int tgt  = blockIdx.y;
    const unsigned* whp = g_Wt_hi[tgt];
    const unsigned* wlp = g_Wt_lo[tgt];

    int t    = threadIdx.x;
    int w    = t >> 5;
    int l    = t & 31;
    int row0 = blockIdx.x * 128;
    int wr   = w * 16;

    float acc[16][4];
    #pragma unroll
    for (int nt = 0; nt < 16; ++nt)
        #pragma unroll
        for (int j = 0; j < 4; ++j) acc[nt][j] = 0.f;

    int arow = t >> 1, ahalf = t & 1;
    int wkk  = t >> 5, wns = l * 4;
    long long agi = (long long)(row0 + arow) * 64 + ahalf * 4;
    bool arow_ok = (row0 + arow) < NN;

    {
        uint4 uh = {0,0,0,0}, ul = {0,0,0,0};
        if (arow_ok) {
            uh = __ldg(reinterpret_cast<const uint4*>(&g_hg12h[0][0] + agi));
            ul = __ldg(reinterpret_cast<const uint4*>(&g_hg12l[0][0] + agi));
        }
        *reinterpret_cast<uint4*>(&Ah[0][arow * ASTW + ahalf * 4]) = uh;
        *reinterpret_cast<uint4*>(&Al[0][arow * ASTW + ahalf * 4]) = ul;
        uint4 pwh = __ldg(reinterpret_cast<const uint4*>(&whp[wkk * 128 + wns]));
        uint4 pwl = __ldg(reinterpret_cast<const uint4*>(&wlp[wkk * 128 + wns]));
        *reinterpret_cast<uint4*>(&Wh[0][wkk * WST + wns]) = pwh;
        *reinterpret_cast<uint4*>(&Wl[0][wkk * WST + wns]) = pwl;
    }
    __syncthreads();

    int rb = wr + (l >> 2);
    int kw = l & 3;

    #pragma unroll 1
    for (int c = 0; c < 96; ++c) {
        int buf = c & 1;
        bool has = (c + 1 < 96);

        uint4 uh = {0,0,0,0}, ul = {0,0,0,0}, pwh, pwl;
        if (has) {
            int cn = c + 1;
            const unsigned* sh_ = &g_hg12h[cn >> 3][0];
            const unsigned* sl_ = &g_hg12l[cn >> 3][0];
            if (arow_ok) {
                uh = __ldg(reinterpret_cast<const uint4*>(sh_ + agi + (cn & 7) * 8));
                ul = __ldg(reinterpret_cast<const uint4*>(sl_ + agi + (cn & 7) * 8));
            }
            pwh = __ldg(reinterpret_cast<const uint4*>(&whp[(cn * 8 + wkk) * 128 + wns]));
            pwl = __ldg(reinterpret_cast<const uint4*>(&wlp[(cn * 8 + wkk) * 128 + wns]));
        }

        const unsigned* ah = &Ah[buf][0];
        const unsigned* al = &Al[buf][0];
        unsigned ahi[4], alo[4];
        ahi[0] = ah[rb * ASTW + kw];
        ahi[1] = ah[(rb + 8) * ASTW + kw];
        ahi[2] = ah[rb * ASTW + 4 + kw];
        ahi[3] = ah[(rb + 8) * ASTW + 4 + kw];
        alo[0] = al[rb * ASTW + kw];
        alo[1] = al[(rb + 8) * ASTW + kw];
        alo[2] = al[rb * ASTW + 4 + kw];
        alo[3] = al[(rb + 8) * ASTW + 4 + kw];
        #pragma unroll
        for (int nt = 0; nt < 16; ++nt) {
            int wb = nt * 8 + (l >> 2);
            unsigned bh0 = Wh[buf][kw * WST + wb];
            unsigned bh1 = Wh[buf][(4 + kw) * WST + wb];
            unsigned bl0 = Wl[buf][kw * WST + wb];
            unsigned bl1 = Wl[buf][(4 + kw) * WST + wb];
            mma_bf16(acc[nt], ahi, bh0, bh1);
            mma_bf16(acc[nt], ahi, bl0, bl1);
            mma_bf16(acc[nt], alo, bh0, bh1);
        }

        if (has) {
            int nbuf = buf ^ 1;
            *reinterpret_cast<uint4*>(&Ah[nbuf][arow * ASTW + ahalf * 4]) = uh;
            *reinterpret_cast<uint4*>(&Al[nbuf][arow * ASTW + ahalf * 4]) = ul;
            *reinterpret_cast<uint4*>(&Wh[nbuf][wkk * WST + wns]) = pwh;
            *reinterpret_cast<uint4*>(&Wl[nbuf][wkk * WST + wns]) = pwl;
        }
        __syncthreads();
    }

    unsigned* dsth = g_hbh[tgt];
    unsigned* dstl = g_hbl[tgt];
    const float* bb = g_bbig[tgt];
    int cw = 2 * (l & 3);
    int rA = row0 + rb;
    #pragma unroll
    for (int nt = 0; nt < 16; ++nt) {
        int col = nt * 8 + cw;
        float2 dv = *reinterpret_cast<const float2*>(&bb[col]);
        unsigned hi, lo;
        if (rA < NN) {
            split_pk(acc[nt][0] + dv.x, acc[nt][1] + dv.y, hi, lo);
            dsth[(long long)rA * 64 + col / 2] = hi;
            dstl[(long long)rA * 64 + col / 2] = lo;
        }
        if (rA + 8 < NN) {
            split_pk(acc[nt][2] + dv.x, acc[nt][3] + dv.y, hi, lo);
            dsth[(long long)(rA + 8) * 64 + col / 2] = hi;
            dstl[(long long)(rA + 8) * 64 + col / 2] = lo;
        }
    }
}

// ---------------- decoder h_new GEMM + fused y head --------------------------
__global__ void __launch_bounds__(256, 2)
k_hnew(int i1, int i2, int hgsel, int idst,
       const float* __restrict__ head_w, const float* __restrict__ head_b,
       float* __restrict__ outy) {
    __shared__ __align__(16) unsigned Ah[2][128 * ASTW];
    __shared__ __align__(16) unsigned Al[2][128 * ASTW];
    __shared__ __align__(16) unsigned Wh[2][8 * WST];
    __shared__ __align__(16) unsigned Wl[2][8 * WST];

    const unsigned* hgh = (hgsel >= 0) ? &g_hg12h[hgsel][0] : g_aggh;
    const unsigned* hgl = (hgsel >= 0) ? &g_hg12l[hgsel][0] : g_aggl;
    const unsigned* h1h = g_hbh[i1];
    const unsigned* h1l = g_hbl[i1];
    const unsigned* h2h = g_hbh[i2];
    const unsigned* h2l = g_hbl[i2];

    int t    = threadIdx.x;
    int w    = t >> 5;
    int l    = t & 31;
    int row0 = blockIdx.x * 128;
    int wr   = w * 16;

    float acc[16][4];
    #pragma unroll
    for (int nt = 0; nt < 16; ++nt)
        #pragma unroll
        for (int j = 0; j < 4; ++j) acc[nt][j] = 0.f;

    int arow = t >> 1, ahalf = t & 1;
    int wkk  = t >> 5, wns = l * 4;
    long long agi = (long long)(row0 + arow) * 64 + ahalf * 4;
    bool arow_ok = (row0 + arow) < NN;

    {
        uint4 uh = {0,0,0,0}, ul = {0,0,0,0};
        if (arow_ok) {
            uh = __ldg(reinterpret_cast<const uint4*>(h1h + agi));
            ul = __ldg(reinterpret_cast<const uint4*>(h1l + agi));
        }
        *reinterpret_cast<uint4*>(&Ah[0][arow * ASTW + ahalf * 4]) = uh;
        *reinterpret_cast<uint4*>(&Al[0][arow * ASTW + ahalf * 4]) = ul;
        uint4 pwh = __ldg(reinterpret_cast<const uint4*>(&g_Whi_pk[wkk * 128 + wns]));
        uint4 pwl = __ldg(reinterpret_cast<const uint4*>(&g_Wlo_pk[wkk * 128 + wns]));
        *reinterpret_cast<uint4*>(&Wh[0][wkk * WST + wns]) = pwh;
        *reinterpret_cast<uint4*>(&Wl[0][wkk * WST + wns]) = pwl;
    }
    __syncthreads();

    int rb = wr + (l >> 2);
    int kw = l & 3;

    for (int c = 0; c < 24; ++c) {
        int buf = c & 1;
        bool has = (c + 1 < 24);

        uint4 uh = {0,0,0,0}, ul = {0,0,0,0}, pwh, pwl;
        if (has) {
            int cn = c + 1;
            const unsigned* sh_ = (cn < 8) ? h1h : (cn < 16) ? h2h : hgh;
            const unsigned* sl_ = (cn < 8) ? h1l : (cn < 16) ? h2l : hgl;
            if (arow_ok) {
                uh = __ldg(reinterpret_cast<const uint4*>(sh_ + agi + (cn & 7) * 8));
                ul = __ldg(reinterpret_cast<const uint4*>(sl_ + agi + (cn & 7) * 8));
            }
            pwh = __ldg(reinterpret_cast<const uint4*>(&g_Whi_pk[(cn * 8 + wkk) * 128 + wns]));
            pwl = __ldg(reinterpret_cast<const uint4*>(&g_Wlo_pk[(cn * 8 + wkk) * 128 + wns]));
        }

        const unsigned* ah = &Ah[buf][0];
        const unsigned* al = &Al[buf][0];
        unsigned ahi[4], alo[4];
        ahi[0] = ah[rb * ASTW + kw];
        ahi[1] = ah[(rb + 8) * ASTW + kw];
        ahi[2] = ah[rb * ASTW + 4 + kw];
        ahi[3] = ah[(rb + 8) * ASTW + 4 + kw];
        alo[0] = al[rb * ASTW + kw];
        alo[1] = al[(rb + 8) * ASTW + kw];
        alo[2] = al[rb * ASTW + 4 + kw];
        alo[3] = al[(rb + 8) * ASTW + 4 + kw];
        #pragma unroll
        for (int nt = 0; nt < 16; ++nt) {
            int wb = nt * 8 + (l >> 2);
            unsigned bh0 = Wh[buf][kw * WST + wb];
            unsigned bh1 = Wh[buf][(4 + kw) * WST + wb];
            unsigned bl0 = Wl[buf][kw * WST + wb];
            unsigned bl1 = Wl[buf][(4 + kw) * WST + wb];
            mma_bf16(acc[nt], ahi, bh0, bh1);
            mma_bf16(acc[nt], ahi, bl0, bl1);
            mma_bf16(acc[nt], alo, bh0, bh1);
        }

        if (has) {
            int nbuf = buf ^ 1;
            *reinterpret_cast<uint4*>(&Ah[nbuf][arow * ASTW + ahalf * 4]) = uh;
            *reinterpret_cast<uint4*>(&Al[nbuf][arow * ASTW + ahalf * 4]) = ul;
            *reinterpret_cast<uint4*>(&Wh[nbuf][wkk * WST + wns]) = pwh;
            *reinterpret_cast<uint4*>(&Wl[nbuf][wkk * WST + wns]) = pwl;
        }
        __syncthreads();
    }

    // epilogue: bias into acc; store packed bf16 hi/lo; fused y head
    unsigned* dsth = g_hbh[idst];
    unsigned* dstl = g_hbl[idst];
    int cw = 2 * (l & 3);
    int rA = row0 + rb;
    #pragma unroll
    for (int nt = 0; nt < 16; ++nt) {
        int col = nt * 8 + cw;
        float2 dv = *reinterpret_cast<const float2*>(&g_dvec[col]);
        acc[nt][0] += dv.x; acc[nt][1] += dv.y;
        acc[nt][2] += dv.x; acc[nt][3] += dv.y;
        unsigned hi, lo;
        if (rA < NN) {
            split_pk(acc[nt][0], acc[nt][1], hi, lo);
            dsth[(long long)rA * 64 + col / 2] = hi;
            dstl[(long long)rA * 64 + col / 2] = lo;
        }
        if (rA + 8 < NN) {
            split_pk(acc[nt][2], acc[nt][3], hi, lo);
            dsth[(long long)(rA + 8) * 64 + col / 2] = hi;
            dstl[(long long)(rA + 8) * 64 + col / 2] = lo;
        }
    }

    // y = h_new @ head_w^T + head_b (reuse dead A-tile smem for head_w)
    float* Hw = reinterpret_cast<float*>(&Ah[0][0]);
    for (int i = t; i < 16 * 128; i += 256) Hw[i] = head_w[i];
    __syncthreads();
    #pragma unroll
    for (int ch = 0; ch < 16; ++ch) {
        float s0 = 0.f, s1 = 0.f;
        #pragma unroll
        for (int nt = 0; nt < 16; ++nt) {
            int col = nt * 8 + cw;
            float w0 = Hw[ch * 128 + col], w1 = Hw[ch * 128 + col + 1];
            s0 += acc[nt][0] * w0 + acc[nt][1] * w1;
            s1 += acc[nt][2] * w0 + acc[nt][3] * w1;
        }
        s0 += __shfl_xor_sync(0xffffffffu, s0, 1);
        s0 += __shfl_xor_sync(0xffffffffu, s0, 2);
        s1 += __shfl_xor_sync(0xffffffffu, s1, 1);
        s1 += __shfl_xor_sync(0xffffffffu, s1, 2);
        if ((l & 3) == 0) {
            float hb = __ldg(&head_b[ch]);
            if (rA < NN)     outy[(long long)rA * 16 + ch] = s0 + hb;
            if (rA + 8 < NN) outy[(long long)(rA + 8) * 16 + ch] = s1 + hb;
        }
    }
}

// ---------------------------------------------------------------------------
extern "C" void kernel_launch(void* const* d_in, const int* in_sizes, int n_in,
                              void* d_out, int out_size) {
    const float* x_seq  = (const float*)d_in[0];
    const void*  ei     = d_in[1];
    const float* gcn_w  = (const float*)d_in[5];
    const float* gcn_b  = (const float*)d_in[6];
    const float* conv_w = (const float*)d_in[7];
    const float* conv_b = (const float*)d_in[8];
    const float* proj_w = (const float*)d_in[9];
    const float* proj_b = (const float*)d_in[10];
    const float* head_w = (const float*)d_in[11];
    const float* head_b = (const float*)d_in[12];
    float* out = (float*)d_out;

    // side stream for the weight-prep chain (fork/join via events; capture-safe)
    cudaStream_t s1;
    cudaStreamCreateWithFlags(&s1, cudaStreamNonBlocking);
    cudaEvent_t evFork, evJoin;
    cudaEventCreateWithFlags(&evFork, cudaEventDisableTiming);
    cudaEventCreateWithFlags(&evJoin, cudaEventDisableTiming);

    // fork: weight chain (prepWsd -> Rchain) runs concurrently with CSR chain
    cudaEventRecord(evFork, 0);
    cudaStreamWaitEvent(s1, evFork, 0);
    k_prepWsd<<<193, 128, 0, s1>>>(conv_w, proj_w, conv_b, proj_b);
    k_Rchain<<<65, 128, 0, s1>>>();
    cudaEventRecord(evJoin, s1);

    // main stream: CSR construction + all 12 encoder GCNs
    k_init<<<(TT * NN + 255) / 256, 256>>>((const unsigned*)ei);
    {
        long long tot = (long long)TT * EE;
        int blocks = (int)((tot + 255) / 256);
        k_count12<<<blocks, 256>>>(ei);
        k_scanA<<<dim3(10, TT), 256>>>();
        k_scanB<<<dim3(10, TT), 256>>>();
        k_fill12<<<blocks, 256>>>(ei);
    }
    {
        dim3 gg(NN / 16, TT);
        k_gcn_all<<<gg, 128>>>(x_seq, gcn_w, gcn_b);
    }

    // join: hbig needs both Wt (side stream) and hg12 (main stream)
    cudaStreamWaitEvent(0, evJoin, 0);

    // one wide GEMM: h(10) -> buffer 0, h(11) -> buffer 1
    k_hbig<<<dim3((NN + 127) / 128, 2), 256>>>();

    // decoder: 6 serial steps with feedback
    int i1 = 0, i2 = 1, idst = 2;
    for (int t = TT; t < TT + HOR; ++t) {
        int hgsel;
        float* outy = out + (long long)(t - TT) * NN * CC;
        if (t == TT) hgsel = TT - 1;     // identical GCN to encoder step 11
        else {
            const float* xin = out + (long long)(t - TT - 1) * NN * CC;
            k_gcn1<<<NN / 16, 128>>>(xin, gcn_w, gcn_b);
            hgsel = -1;
        }
        k_hnew<<<(NN + 127) / 128, 256>>>(i1, i2, hgsel, idst,
                                          head_w, head_b, outy);
        int old1 = i1; i1 = i2; i2 = idst; idst = old1;
    }
}